// round 2
// baseline (speedup 1.0000x reference)
#include <cuda_runtime.h>
#include <math.h>

typedef unsigned long long ull;

#define T_LEN 262144
#define B_N 8
#define C_N 8
#define K_N 50
#define THREADS 128
#define CPAD 10   // channel dim padded 8->10: conflict-free strided LDS.64

// Ping-pong hidden-state buffers [B][C][T]
__device__ float g_h0[B_N * C_N * T_LEN];
__device__ float g_h1[B_N * C_N * T_LEN];
// Layer-0 weights [k][o]
__device__ float g_W0[K_N * C_N];
// Layers 1..17 weights, c-paired: [layer][k][cpair][o] -> ull = (w[2cp], w[2cp+1])
__device__ ull g_W2[17 * K_N * 4 * C_N];

// ---------------------------------------------------------------------------
__device__ __forceinline__ void ffma2(ull& acc, ull w, ull h) {
    asm("fma.rn.f32x2 %0, %1, %2, %0;" : "+l"(acc) : "l"(w), "l"(h));
}
__device__ __forceinline__ float2 unpack2(ull v) {
    float2 r;
    asm("mov.b64 {%0, %1}, %2;" : "=f"(r.x), "=f"(r.y) : "l"(v));
    return r;
}
__device__ __forceinline__ float fast_tanh(float x) {
    x = fminf(fmaxf(x, -30.0f), 30.0f);
    float e = __expf(-2.0f * x);
    return (1.0f - e) / (1.0f + e);
}
__device__ __forceinline__ float fast_sigmoid(float x) {
    x = fminf(fmaxf(x, -30.0f), 30.0f);
    return 1.0f / (1.0f + __expf(-x));
}

// ---------------------------------------------------------------------------
// Weight-norm prep: one block per (layer, out-channel).
// ---------------------------------------------------------------------------
__global__ void prep_weights(const float* __restrict__ v0,
                             const float* __restrict__ g0,
                             const float* __restrict__ vs,
                             const float* __restrict__ gs) {
    int l = blockIdx.x;   // 0..17
    int o = blockIdx.y;   // 0..7
    int cin = (l == 0) ? 1 : C_N;
    const float* v;
    float g;
    if (l == 0) {
        v = v0 + o * K_N;
        g = g0[o];
    } else {
        v = vs + (size_t)((l - 1) * C_N + o) * C_N * K_N;
        g = gs[(l - 1) * C_N + o];
    }
    int n = cin * K_N;
    float s = 0.0f;
    for (int i = threadIdx.x; i < n; i += blockDim.x) {
        float x = v[i];
        s += x * x;
    }
    __shared__ float red[2];
    #pragma unroll
    for (int off = 16; off > 0; off >>= 1)
        s += __shfl_down_sync(0xffffffffu, s, off);
    if ((threadIdx.x & 31) == 0) red[threadIdx.x >> 5] = s;
    __syncthreads();
    float scale = g * rsqrtf(red[0] + red[1]);

    if (l == 0) {
        for (int i = threadIdx.x; i < n; i += blockDim.x)
            g_W0[i * C_N + o] = scale * v[i];   // i == k
    } else {
        float* W2f = (float*)g_W2;
        for (int i = threadIdx.x; i < n; i += blockDim.x) {
            int c = i / K_N;
            int k = i % K_N;
            int idx = (((l - 1) * K_N + k) * 4 + (c >> 1)) * C_N + o;
            W2f[idx * 2 + (c & 1)] = scale * v[i];
        }
    }
}

// ---------------------------------------------------------------------------
// Layer 0: C_in = 1, dilation 1 (scalar path; 1/8 of the per-layer work).
// ---------------------------------------------------------------------------
__global__ void __launch_bounds__(THREADS)
layer0_kernel(const float* __restrict__ h_in, float* __restrict__ h_out,
              const float* __restrict__ bias, const float* __restrict__ gw,
              const float* __restrict__ gb) {
    constexpr int NP = 4;
    constexpr int TILE = THREADS * NP;       // 512
    constexpr int HALO = K_N - 1;            // 49
    constexpr int HW = TILE + HALO;

    __shared__ __align__(16) float h_s[HW];
    __shared__ __align__(16) float w_s[K_N][C_N];
    __shared__ float gw_s[C_N][C_N];
    __shared__ float b_s[C_N];
    __shared__ float gb_s[C_N];

    const int b = blockIdx.y;
    const int tile0 = blockIdx.x * TILE;
    const int tid = threadIdx.x;

    for (int i = tid; i < K_N * C_N; i += THREADS) (&w_s[0][0])[i] = g_W0[i];
    for (int i = tid; i < C_N * C_N; i += THREADS) (&gw_s[0][0])[i] = gw[i];
    if (tid < C_N) { b_s[tid] = bias[tid]; gb_s[tid] = gb[tid]; }

    const float* hb = h_in + (size_t)b * T_LEN;
    for (int j = tid; j < HW; j += THREADS) {
        int t = tile0 - HALO + j;
        h_s[j] = (t >= 0) ? hb[t] : 0.0f;
    }
    __syncthreads();

    float acc[C_N][NP];
    #pragma unroll
    for (int o = 0; o < C_N; o++) {
        float bv = b_s[o];
        #pragma unroll
        for (int p = 0; p < NP; p++) acc[o][p] = bv;
    }

    #pragma unroll 1
    for (int k = 0; k < K_N; k++) {
        float hv[NP];
        #pragma unroll
        for (int p = 0; p < NP; p++) hv[p] = h_s[tid + k + p * THREADS];
        float wv[C_N];
        *(float4*)&wv[0] = *(const float4*)&w_s[k][0];
        *(float4*)&wv[4] = *(const float4*)&w_s[k][4];
        #pragma unroll
        for (int o = 0; o < C_N; o++)
            #pragma unroll
            for (int p = 0; p < NP; p++)
                acc[o][p] = fmaf(wv[o], hv[p], acc[o][p]);
    }

    float* ob = h_out + (size_t)b * C_N * T_LEN;
    #pragma unroll
    for (int p = 0; p < NP; p++) {
        float prev = h_s[tid + HALO + p * THREADS];
        #pragma unroll
        for (int o = 0; o < C_N; o++) {
            float gate = gb_s[o];
            #pragma unroll
            for (int c = 0; c < C_N; c++) gate = fmaf(gw_s[o][c], acc[c][p], gate);
            ob[(size_t)o * T_LEN + tile0 + tid + p * THREADS] =
                fast_tanh(acc[o][p]) * fast_sigmoid(gate) + prev;
        }
    }
}

// ---------------------------------------------------------------------------
// Layers 1..17: packed f32x2 over input-channel pairs.
//   h in SMEM channel-interleaved [time][CPAD]  -> LDS.64 (h[2cp], h[2cp+1])
//   w in SMEM [k][cpair][o] as ull              -> broadcast LDS.128
//   acc[o][p] is a packed pair; reduce lo+hi at the end.
// ---------------------------------------------------------------------------
template <int DIL, int NP>
__global__ void __launch_bounds__(THREADS)
layer2_kernel(const float* __restrict__ h_in, float* __restrict__ h_out,
              const ull* __restrict__ W2,     // [K][4][8] ull
              const float* __restrict__ bias, const float* __restrict__ gw,
              const float* __restrict__ gb) {
    constexpr int TILE = THREADS * NP;
    constexpr int HALO = (K_N - 1) * DIL;
    constexpr int HW = TILE + HALO;

    __shared__ __align__(16) float h_s[HW][CPAD];
    __shared__ __align__(16) ull w_s[K_N][4][C_N];
    __shared__ float gw_s[C_N][C_N];
    __shared__ float b_s[C_N];
    __shared__ float gb_s[C_N];

    const int b = blockIdx.y;
    const int tile0 = blockIdx.x * TILE;
    const int tid = threadIdx.x;

    for (int i = tid; i < K_N * 4 * C_N; i += THREADS) (&w_s[0][0][0])[i] = W2[i];
    for (int i = tid; i < C_N * C_N; i += THREADS) (&gw_s[0][0])[i] = gw[i];
    if (tid < C_N) { b_s[tid] = bias[tid]; gb_s[tid] = gb[tid]; }

    const float* hb = h_in + (size_t)b * C_N * T_LEN;
    #pragma unroll
    for (int c = 0; c < C_N; c++) {
        const float* hc = hb + (size_t)c * T_LEN;
        for (int j = tid; j < HW; j += THREADS) {
            int t = tile0 - HALO + j;
            h_s[j][c] = (t >= 0) ? hc[t] : 0.0f;
        }
    }
    __syncthreads();

    ull acc[C_N][NP];
    #pragma unroll
    for (int o = 0; o < C_N; o++)
        #pragma unroll
        for (int p = 0; p < NP; p++) acc[o][p] = 0ull;

    #pragma unroll 1
    for (int k = 0; k < K_N; k++) {
        const float* hrow = &h_s[tid + k * DIL][0];
        const ull* wk = &w_s[k][0][0];
        #pragma unroll
        for (int cp = 0; cp < 4; cp++) {
            ull h2[NP];
            #pragma unroll
            for (int p = 0; p < NP; p++)
                h2[p] = *(const ull*)(hrow + p * (THREADS * CPAD) + 2 * cp);
            ull w[C_N];
            #pragma unroll
            for (int oo = 0; oo < 4; oo++) {
                ulonglong2 wv = *(const ulonglong2*)(wk + cp * C_N + oo * 2);
                w[oo * 2] = wv.x;
                w[oo * 2 + 1] = wv.y;
            }
            #pragma unroll
            for (int o = 0; o < C_N; o++)
                #pragma unroll
                for (int p = 0; p < NP; p++)
                    ffma2(acc[o][p], w[o], h2[p]);
        }
    }

    float* ob = h_out + (size_t)b * C_N * T_LEN;
    #pragma unroll
    for (int p = 0; p < NP; p++) {
        float outv[C_N];
        #pragma unroll
        for (int o = 0; o < C_N; o++) {
            float2 u = unpack2(acc[o][p]);
            outv[o] = b_s[o] + u.x + u.y;
        }
        const float* hres = &h_s[tid + HALO + p * THREADS][0];
        #pragma unroll
        for (int o = 0; o < C_N; o++) {
            float gate = gb_s[o];
            #pragma unroll
            for (int c = 0; c < C_N; c++) gate = fmaf(gw_s[o][c], outv[c], gate);
            ob[(size_t)o * T_LEN + tile0 + tid + p * THREADS] =
                fast_tanh(outv[o]) * fast_sigmoid(gate) + hres[o];
        }
    }
}

// ---------------------------------------------------------------------------
// Head: means = mean_w . h + mean_b ; stds = exp(0.5*(lv_w . h + lv_b))
// ---------------------------------------------------------------------------
__global__ void __launch_bounds__(256)
head_kernel(const float* __restrict__ h,
            const float* __restrict__ mean_w, const float* __restrict__ mean_b,
            const float* __restrict__ lv_w, const float* __restrict__ lv_b,
            float* __restrict__ out) {
    const int b = blockIdx.y;
    const int t0 = (blockIdx.x * 256 + threadIdx.x) * 4;
    if (t0 >= T_LEN) return;
    const float* hb = h + (size_t)b * C_N * T_LEN;
    float m[4], lv[4];
    float mb = mean_b[0], lb = lv_b[0];
    #pragma unroll
    for (int p = 0; p < 4; p++) { m[p] = mb; lv[p] = lb; }
    #pragma unroll
    for (int c = 0; c < C_N; c++) {
        float4 hv = *(const float4*)&hb[(size_t)c * T_LEN + t0];
        float mw = mean_w[c], lw = lv_w[c];
        m[0] = fmaf(mw, hv.x, m[0]); lv[0] = fmaf(lw, hv.x, lv[0]);
        m[1] = fmaf(mw, hv.y, m[1]); lv[1] = fmaf(lw, hv.y, lv[1]);
        m[2] = fmaf(mw, hv.z, m[2]); lv[2] = fmaf(lw, hv.z, lv[2]);
        m[3] = fmaf(mw, hv.w, m[3]); lv[3] = fmaf(lw, hv.w, lv[3]);
    }
    float s[4];
    #pragma unroll
    for (int p = 0; p < 4; p++) s[p] = expf(0.5f * lv[p]);
    *(float4*)&out[(size_t)b * T_LEN + t0] = make_float4(m[0], m[1], m[2], m[3]);
    *(float4*)&out[(size_t)B_N * T_LEN + (size_t)b * T_LEN + t0] =
        make_float4(s[0], s[1], s[2], s[3]);
}

// ---------------------------------------------------------------------------
extern "C" void kernel_launch(void* const* d_in, const int* in_sizes, int n_in,
                              void* d_out, int out_size) {
    (void)in_sizes; (void)n_in; (void)out_size;
    const float* x      = (const float*)d_in[0];
    const float* v0     = (const float*)d_in[1];
    const float* g0     = (const float*)d_in[2];
    const float* b0     = (const float*)d_in[3];
    const float* gw0    = (const float*)d_in[4];
    const float* gb0    = (const float*)d_in[5];
    const float* vs     = (const float*)d_in[6];
    const float* gs     = (const float*)d_in[7];
    const float* bs     = (const float*)d_in[8];
    const float* gws    = (const float*)d_in[9];
    const float* gbs    = (const float*)d_in[10];
    const float* mean_w = (const float*)d_in[11];
    const float* mean_b = (const float*)d_in[12];
    const float* lv_w   = (const float*)d_in[13];
    const float* lv_b   = (const float*)d_in[14];

    float *bufA, *bufB;
    ull* W2dev;
    cudaGetSymbolAddress((void**)&bufA, g_h0);
    cudaGetSymbolAddress((void**)&bufB, g_h1);
    cudaGetSymbolAddress((void**)&W2dev, g_W2);

    prep_weights<<<dim3(18, 8), 64>>>(v0, g0, vs, gs);

    // Layer 0
    layer0_kernel<<<dim3(T_LEN / 512, B_N), THREADS>>>(x, bufA, b0, gw0, gb0);

    static const int dils[18] = {1,1,1,1,1,1,1,2,2,2,2,4,4,4,4,8,8,8};
    float* cur = bufA;
    float* nxt = bufB;
    for (int i = 1; i < 18; i++) {
        const ull* Wl    = W2dev + (size_t)(i - 1) * K_N * 4 * C_N;
        const float* bl  = bs  + (i - 1) * C_N;
        const float* gwl = gws + (i - 1) * C_N * C_N;
        const float* gbl = gbs + (i - 1) * C_N;
        switch (dils[i]) {
            case 1:
                layer2_kernel<1, 4><<<dim3(T_LEN / 512, B_N), THREADS>>>(
                    cur, nxt, Wl, bl, gwl, gbl);
                break;
            case 2:
                layer2_kernel<2, 4><<<dim3(T_LEN / 512, B_N), THREADS>>>(
                    cur, nxt, Wl, bl, gwl, gbl);
                break;
            case 4:
                layer2_kernel<4, 4><<<dim3(T_LEN / 512, B_N), THREADS>>>(
                    cur, nxt, Wl, bl, gwl, gbl);
                break;
            case 8:
                layer2_kernel<8, 2><<<dim3(T_LEN / 256, B_N), THREADS>>>(
                    cur, nxt, Wl, bl, gwl, gbl);
                break;
        }
        float* t = cur; cur = nxt; nxt = t;
    }

    head_kernel<<<dim3(T_LEN / (256 * 4), B_N), 256>>>(
        cur, mean_w, mean_b, lv_w, lv_b, (float*)d_out);
}